// round 1
// baseline (speedup 1.0000x reference)
#include <cuda_runtime.h>
#include <cstdint>

// Problem constants (fixed instance)
#define HID   16
#define BATCH 2048
#define SEQT  2048
#define FUT   32
#define NOUT  (FUT + 1)   // 33 outputs per batch element

typedef unsigned long long ull;

// ---------- packed f32x2 helpers (sm_100+/sm_103a) ----------
__device__ __forceinline__ ull pack2(float lo, float hi) {
    ull r;
    asm("mov.b64 %0, {%1, %2};" : "=l"(r) : "f"(lo), "f"(hi));
    return r;
}
__device__ __forceinline__ void unpack2(ull v, float& lo, float& hi) {
    asm("mov.b64 {%0, %1}, %2;" : "=f"(lo), "=f"(hi) : "l"(v));
}
__device__ __forceinline__ ull fma2(ull a, ull b, ull c) {
    ull d;
    asm("fma.rn.f32x2 %0, %1, %2, %3;" : "=l"(d) : "l"(a), "l"(b), "l"(c));
    return d;
}

// ---------- fast activations ----------
__device__ __forceinline__ float tanh_ap(float x) {
    float y;
    asm("tanh.approx.f32 %0, %1;" : "=f"(y) : "f"(x));
    return y;
}
__device__ __forceinline__ float sigm(float x) {
    // sigma(x) = 0.5*tanh(0.5x) + 0.5
    return fmaf(0.5f, tanh_ap(0.5f * x), 0.5f);
}

__global__ void __launch_bounds__(128, 2)
lstm_net_kernel(const float* __restrict__ x,
                const float* __restrict__ Wih1, const float* __restrict__ Whh1,
                const float* __restrict__ bih1, const float* __restrict__ bhh1,
                const float* __restrict__ Wih2, const float* __restrict__ Whh2,
                const float* __restrict__ bih2, const float* __restrict__ bhh2,
                const float* __restrict__ fc1w, const float* __restrict__ fc1b,
                const float* __restrict__ fc2w, const float* __restrict__ fc2b,
                float* __restrict__ out)
{
    // Shared: tiny FC head weights (used only 33x per element)
    __shared__ float s_fc1w[(HID / 2) * HID];   // 8 x 16
    __shared__ float s_fc1b[HID / 2];           // 8
    __shared__ float s_fc2w[HID / 2];           // 8
    __shared__ float s_fc2b;

    const int tid = threadIdx.x;
    if (tid < (HID / 2) * HID) s_fc1w[tid] = fc1w[tid];
    if (tid < HID / 2) { s_fc1b[tid] = fc1b[tid]; s_fc2w[tid] = fc2w[tid]; }
    if (tid == 0) s_fc2b = fc2b[0];
    __syncthreads();

    const int lane  = tid & 31;
    const int warp  = blockIdx.x * (blockDim.x >> 5) + (tid >> 5);
    const int half  = lane >> 4;          // 0 or 1 : which batch element in the warp
    const int j     = lane & 15;          // hidden unit owned by this lane
    const int hbase = lane & 16;          // shuffle source base for my half-warp
    const int b     = warp * 2 + half;    // batch element
    if (b >= BATCH) return;

    // Gate rows for unit j (torch order i,f,g,o)
    const int r0 = j, r1 = j + HID, r2 = j + 2 * HID, r3 = j + 3 * HID;

    // ---- load weights into registers, packed (i,f) and (g,o) ----
    const ull a_if = pack2(Wih1[r0], Wih1[r1]);
    const ull a_go = pack2(Wih1[r2], Wih1[r3]);
    const ull b1_if = pack2(bih1[r0] + bhh1[r0], bih1[r1] + bhh1[r1]);
    const ull b1_go = pack2(bih1[r2] + bhh1[r2], bih1[r3] + bhh1[r3]);
    const ull b2_if = pack2(bih2[r0] + bhh2[r0], bih2[r1] + bhh2[r1]);
    const ull b2_go = pack2(bih2[r2] + bhh2[r2], bih2[r3] + bhh2[r3]);

    ull w1_if[HID], w1_go[HID];
    ull w2i_if[HID], w2i_go[HID], w2h_if[HID], w2h_go[HID];
#pragma unroll
    for (int k = 0; k < HID; ++k) {
        w1_if[k]  = pack2(Whh1[r0 * HID + k], Whh1[r1 * HID + k]);
        w1_go[k]  = pack2(Whh1[r2 * HID + k], Whh1[r3 * HID + k]);
        w2i_if[k] = pack2(Wih2[r0 * HID + k], Wih2[r1 * HID + k]);
        w2i_go[k] = pack2(Wih2[r2 * HID + k], Wih2[r3 * HID + k]);
        w2h_if[k] = pack2(Whh2[r0 * HID + k], Whh2[r1 * HID + k]);
        w2h_go[k] = pack2(Whh2[r2 * HID + k], Whh2[r3 * HID + k]);
    }

    // ---- state ----
    float h1 = 0.f, c1 = 0.f, h2 = 0.f, c2 = 0.f;
    float o_head = 0.f;

    const float* xrow = x + (size_t)b * SEQT;
    float xt = xrow[0];

    float* orow = out + (size_t)b * NOUT;

#pragma unroll 1
    for (int t = 0; t < SEQT + FUT; ++t) {
        // prefetch next teacher input (mask keeps index in-bounds; garbage past T unused)
        const float xnext = xrow[(t + 1) & (SEQT - 1)];
        const float inp = (t < SEQT) ? xt : o_head;

        // ======== layer 1 ========
        ull aif = b1_if, ago = b1_go;
        {
            const ull xp = pack2(inp, inp);
            aif = fma2(a_if, xp, aif);
            ago = fma2(a_go, xp, ago);
        }
#pragma unroll
        for (int k = 0; k < HID; ++k) {
            const float hk = __shfl_sync(0xffffffffu, h1, hbase + k);
            const ull hp = pack2(hk, hk);
            aif = fma2(w1_if[k], hp, aif);
            ago = fma2(w1_go[k], hp, ago);
        }
        {
            float gi, gf, gg, go;
            unpack2(aif, gi, gf);
            unpack2(ago, gg, go);
            const float i1 = sigm(gi), f1 = sigm(gf);
            const float g1 = tanh_ap(gg), o1 = sigm(go);
            c1 = fmaf(f1, c1, i1 * g1);
            h1 = o1 * tanh_ap(c1);
        }

        // ======== layer 2 ========
        aif = b2_if; ago = b2_go;
#pragma unroll
        for (int k = 0; k < HID; ++k) {
            const float ak = __shfl_sync(0xffffffffu, h1, hbase + k);
            const float bk = __shfl_sync(0xffffffffu, h2, hbase + k);
            const ull ap = pack2(ak, ak);
            const ull bp = pack2(bk, bk);
            aif = fma2(w2i_if[k], ap, aif);
            ago = fma2(w2i_go[k], ap, ago);
            aif = fma2(w2h_if[k], bp, aif);
            ago = fma2(w2h_go[k], bp, ago);
        }
        {
            float gi, gf, gg, go;
            unpack2(aif, gi, gf);
            unpack2(ago, gg, go);
            const float i2 = sigm(gi), f2 = sigm(gf);
            const float g2 = tanh_ap(gg), o2 = sigm(go);
            c2 = fmaf(f2, c2, i2 * g2);
            h2 = o2 * tanh_ap(c2);
        }

        // ======== head (only for last teacher step + future steps) ========
        if (t >= SEQT - 1) {
            const int jj = j & 7;
            float acc = s_fc1b[jj];
#pragma unroll
            for (int k = 0; k < HID; ++k) {
                const float hk = __shfl_sync(0xffffffffu, h2, hbase + k);
                acc = fmaf(s_fc1w[jj * HID + k], hk, acc);
            }
            acc = (acc >= 0.f) ? acc : 0.2f * acc;                 // LeakyReLU(0.2)
            float p = (j < 8) ? s_fc2w[jj] * acc : 0.f;
            p += __shfl_xor_sync(0xffffffffu, p, 8);
            p += __shfl_xor_sync(0xffffffffu, p, 4);
            p += __shfl_xor_sync(0xffffffffu, p, 2);
            p += __shfl_xor_sync(0xffffffffu, p, 1);
            o_head = p + s_fc2b;
            if (j == 0) orow[t - (SEQT - 1)] = o_head;
        }

        xt = xnext;
    }
}

extern "C" void kernel_launch(void* const* d_in, const int* in_sizes, int n_in,
                              void* d_out, int out_size)
{
    const float* x    = (const float*)d_in[0];
    const float* Wih1 = (const float*)d_in[1];
    const float* Whh1 = (const float*)d_in[2];
    const float* bih1 = (const float*)d_in[3];
    const float* bhh1 = (const float*)d_in[4];
    const float* Wih2 = (const float*)d_in[5];
    const float* Whh2 = (const float*)d_in[6];
    const float* bih2 = (const float*)d_in[7];
    const float* bhh2 = (const float*)d_in[8];
    const float* fc1w = (const float*)d_in[9];
    const float* fc1b = (const float*)d_in[10];
    const float* fc2w = (const float*)d_in[11];
    const float* fc2b = (const float*)d_in[12];
    float* out = (float*)d_out;

    // 128 threads = 4 warps = 8 batch elements per block
    const int blocks = BATCH / 8;   // 256
    lstm_net_kernel<<<blocks, 128>>>(x, Wih1, Whh1, bih1, bhh1,
                                     Wih2, Whh2, bih2, bhh2,
                                     fc1w, fc1b, fc2w, fc2b, out);
}